// round 16
// baseline (speedup 1.0000x reference)
#include <cuda_runtime.h>
#include <cuda_fp16.h>
#include <cstdint>

// ---------------------------------------------------------------------------
// TemporalAttention, B200 (compute_100 target -> legacy mma.sync path).
// R16 = R15 resubmitted unchanged: A/B test for run-to-run variance vs real
// regression (R15 measured 233us total despite attn improving 38.3->33.5us,
// with no plausible mechanism in the diff).
// Order: fused_prep, gn_apply, gemm0, attn, gemm1
// ---------------------------------------------------------------------------

#define T_DIM   16
#define C_DIM   512
#define HW_DIM  1024
#define NTOK    16384
#define NQKV    1536
#define NGRP    32
#define GN_EPS  1e-5f

__device__ __half  g_xn  [NTOK * C_DIM];
__device__ __half  g_qkv [NTOK * NQKV];     // raw Q|K|V (biases applied in attn)
__device__ __half  g_attn[NTOK * C_DIM];
__device__ __half  g_wcat[NQKV * C_DIM];
__device__ __half  g_wproj[C_DIM * C_DIM];
__device__ float   g_mu[512];
__device__ float   g_rs[512];
__device__ __half2 g_qbh[256];              // half2(b_q + t_mid @ Wq^T)
__device__ __half2 g_kbh[4 * 256];          // half2(b_k + t_rest[fi] @ Wk^T)
__device__ float   g_pb[512];               // b_proj + b_v @ Wproj^T

// ---------------------------------------------------------------------------
// fused_prep: [0,512) GN stats; [512,1536) weight fp16 convert;
// [1536,1600) qb/kb bias; [1600,1664) pb = b_proj + Wproj·b_v.
// All ranges input/output disjoint.
// ---------------------------------------------------------------------------
__global__ void __launch_bounds__(256) fused_prep(const float* __restrict__ x,
                                                  const float* __restrict__ w_q,
                                                  const float* __restrict__ w_k,
                                                  const float* __restrict__ w_v,
                                                  const float* __restrict__ w_proj,
                                                  const float* __restrict__ b_q,
                                                  const float* __restrict__ b_k,
                                                  const float* __restrict__ b_v,
                                                  const float* __restrict__ b_proj) {
    if (blockIdx.x < 512) {
        int b = blockIdx.x;
        const float4* base = (const float4*)(x + (size_t)b * 16384);
        float s = 0.f, s2 = 0.f;
        #pragma unroll
        for (int i = 0; i < 16; i++) {
            float4 v = base[threadIdx.x + i * 256];
            s  += v.x + v.y + v.z + v.w;
            s2 += v.x * v.x + v.y * v.y + v.z * v.z + v.w * v.w;
        }
        for (int o = 16; o; o >>= 1) {
            s  += __shfl_xor_sync(0xffffffffu, s,  o);
            s2 += __shfl_xor_sync(0xffffffffu, s2, o);
        }
        __shared__ float rs[8], rs2[8];
        int wid = threadIdx.x >> 5;
        if ((threadIdx.x & 31) == 0) { rs[wid] = s; rs2[wid] = s2; }
        __syncthreads();
        if (threadIdx.x == 0) {
            float a = 0.f, a2 = 0.f;
            #pragma unroll
            for (int i = 0; i < 8; i++) { a += rs[i]; a2 += rs2[i]; }
            float mu  = a  * (1.f / 16384.f);
            float var = a2 * (1.f / 16384.f) - mu * mu;
            g_mu[b] = mu;
            g_rs[b] = rsqrtf(var + GN_EPS);
        }
        return;
    }
    if (blockIdx.x < 1536) {
        int i = (blockIdx.x - 512) * 256 + threadIdx.x;
        g_wcat[i]          = __float2half_rn(w_q[i]);
        g_wcat[262144 + i] = __float2half_rn(w_k[i]);
        g_wcat[524288 + i] = __float2half_rn(w_v[i]);
        g_wproj[i]         = __float2half_rn(w_proj[i]);
        return;
    }
    int wid = threadIdx.x >> 5, lane = threadIdx.x & 31;
    if (blockIdx.x < 1600) {
        // ---- qb/kb: one warp per output channel j ----
        int j = (blockIdx.x - 1536) * 8 + wid;        // 0..511
        float aq = 0.f, a0 = 0.f, a1 = 0.f, a2 = 0.f, a3 = 0.f;
        for (int c = lane; c < 512; c += 32) {
            float wq = w_q[j * 512 + c];
            float wk = w_k[j * 512 + c];
            int ci = (c < 256) ? c : c - 256;
            float fr = __expf(-0.035977892f * (float)ci);    // ln(1e4)/256
            float s1, c1, s2, c2;
            __sincosf(fr, &s1, &c1);
            __sincosf(2.f * fr, &s2, &c2);
            if (c < 256) {
                aq += wq;
                a0 += c2 * wk; a1 += c1 * wk; a2 += c1 * wk; a3 += c2 * wk;
            } else {
                a0 -= s2 * wk; a1 -= s1 * wk; a2 += s1 * wk; a3 += s2 * wk;
            }
        }
        for (int o = 16; o; o >>= 1) {
            aq += __shfl_xor_sync(0xffffffffu, aq, o);
            a0 += __shfl_xor_sync(0xffffffffu, a0, o);
            a1 += __shfl_xor_sync(0xffffffffu, a1, o);
            a2 += __shfl_xor_sync(0xffffffffu, a2, o);
            a3 += __shfl_xor_sync(0xffffffffu, a3, o);
        }
        if (lane == 0) {
            float bk = b_k[j];
            __half* qh = (__half*)g_qbh;
            __half* kh = (__half*)g_kbh;
            qh[j]            = __float2half_rn(aq + b_q[j]);
            kh[0 * 512 + j]  = __float2half_rn(a0 + bk);
            kh[1 * 512 + j]  = __float2half_rn(a1 + bk);
            kh[2 * 512 + j]  = __float2half_rn(a2 + bk);
            kh[3 * 512 + j]  = __float2half_rn(a3 + bk);
        }
        return;
    }
    // ---- pb[c] = b_proj[c] + sum_j w_proj[c,j] * b_v[j] ----
    int c = (blockIdx.x - 1600) * 8 + wid;            // 0..511
    float acc = 0.f;
    for (int j = lane; j < 512; j += 32)
        acc += w_proj[c * 512 + j] * b_v[j];
    for (int o = 16; o; o >>= 1)
        acc += __shfl_xor_sync(0xffffffffu, acc, o);
    if (lane == 0) g_pb[c] = acc + b_proj[c];
}

// ---------------------------------------------------------------------------
// GN apply + transpose [t,c,hw] -> [token, c], fp16 output
// ---------------------------------------------------------------------------
__global__ void __launch_bounds__(256) gn_apply(const float* __restrict__ x,
                                                const float* __restrict__ gs,
                                                const float* __restrict__ gb) {
    __shared__ float tile[32][33];
    int t   = blockIdx.z;
    int c0  = blockIdx.y * 32;
    int hw0 = blockIdx.x * 32;
    #pragma unroll
    for (int i = 0; i < 4; i++) {
        int c = c0 + threadIdx.y + i * 8;
        float v = x[((size_t)t * C_DIM + c) * HW_DIM + hw0 + threadIdx.x];
        int grp = c >> 4;
        v = (v - g_mu[t * NGRP + grp]) * g_rs[t * NGRP + grp] * gs[c] + gb[c];
        tile[threadIdx.y + i * 8][threadIdx.x] = v;
    }
    __syncthreads();
    #pragma unroll
    for (int i = 0; i < 4; i++) {
        int hw = hw0 + threadIdx.y + i * 8;
        g_xn[((size_t)t * HW_DIM + hw) * C_DIM + c0 + threadIdx.x] =
            __float2half_rn(tile[threadIdx.x][threadIdx.y + i * 8]);
    }
}

// ---------------------------------------------------------------------------
// FP16 GEMM (R11 core): 128x128x32 CTA tile, 4 warps, warp tile 64x64,
// 4-stage cp.async pipeline, ldmatrix.x4 + mma.sync.m16n8k16.
// MODE 1 epilogue uses g_pb (b_proj + Wproj·b_v).
// ---------------------------------------------------------------------------
__device__ __forceinline__ void cpa16(uint32_t dst, const void* src) {
    asm volatile("cp.async.cg.shared.global [%0], [%1], 16;\n" :: "r"(dst), "l"(src));
}
__device__ __forceinline__ void mma_f16(float* c, const uint32_t* a, const uint32_t* b) {
    asm volatile(
        "mma.sync.aligned.m16n8k16.row.col.f32.f16.f16.f32 "
        "{%0,%1,%2,%3}, {%4,%5,%6,%7}, {%8,%9}, {%0,%1,%2,%3};"
        : "+f"(c[0]), "+f"(c[1]), "+f"(c[2]), "+f"(c[3])
        : "r"(a[0]), "r"(a[1]), "r"(a[2]), "r"(a[3]), "r"(b[0]), "r"(b[1]));
}
__device__ __forceinline__ void ldsm4(uint32_t& r0, uint32_t& r1, uint32_t& r2,
                                      uint32_t& r3, uint32_t a) {
    asm volatile("ldmatrix.sync.aligned.m8n8.x4.shared.b16 {%0,%1,%2,%3}, [%4];"
                 : "=r"(r0), "=r"(r1), "=r"(r2), "=r"(r3) : "r"(a));
}

#define GEMM_DYNSMEM 81920

template <int MODE>
__global__ void __launch_bounds__(128, 2) gemm_fp16(const float* __restrict__ xres,
                                                    float* __restrict__ out) {
    constexpr int LDS_ = 20;                 // pitch in half2 units (80B/row)
    constexpr uint32_t STAGE = 128 * LDS_ * 4 * 2;   // 20480B (A+B)
    const __half* A = (MODE == 0) ? g_xn   : g_attn;
    const __half* B = (MODE == 0) ? g_wcat : g_wproj;

    extern __shared__ __align__(16) uint8_t dynsm[];
    uint32_t dsb = (uint32_t)__cvta_generic_to_shared(dynsm);

    int m0 = blockIdx.y * 128;
    int n0 = blockIdx.x * 128;
    int tid = threadIdx.x;
    int wid = tid >> 5, lane = tid & 31;
    int wm = (wid & 1) * 64, wn = (wid >> 1) * 64;   // 2x2 warp grid
    int g = lane >> 2, tg = lane & 3;

    int a_row = wm + (lane & 15);                       // + im*16
    int a_col = (lane >> 4) << 2;                       // 0 or 4 (uint32)
    int b_row = wn + ((lane >> 4) << 3) + (lane & 7);   // + 16*pair (4 pairs)
    int b_col = ((lane >> 3) & 1) << 2;                 // 0 or 4

    auto load_tile = [&](int kt, int slot) {
        uint32_t base = dsb + (uint32_t)slot * STAGE;
        #pragma unroll
        for (int j = 0; j < 4; j++) {
            int id = tid + j * 128;
            int row = id >> 2, c = id & 3;
            uint32_t soff = (uint32_t)((row * LDS_ + c * 4) * 4);
            cpa16(base + soff, A + (size_t)(m0 + row) * 512 + kt * 32 + c * 8);
            cpa16(base + 10240u + soff, B + (size_t)(n0 + row) * 512 + kt * 32 + c * 8);
        }
        asm volatile("cp.async.commit_group;\n" ::);
    };

    float acc[4][8][4];
    #pragma unroll
    for (int i = 0; i < 4; i++)
        #pragma unroll
        for (int j = 0; j < 8; j++)
            #pragma unroll
            for (int r = 0; r < 4; r++) acc[i][j][r] = 0.f;

    load_tile(0, 0); load_tile(1, 1); load_tile(2, 2);

    for (int kt = 0; kt < 16; ++kt) {        // K = 512 / 32
        if (kt <= 13)      asm volatile("cp.async.wait_group 2;\n" ::);
        else if (kt == 14) asm volatile("cp.async.wait_group 1;\n" ::);
        else               asm volatile("cp.async.wait_group 0;\n" ::);
        __syncthreads();                     // stage kt visible; kt-1 consumed by all

        if (kt + 3 < 16) load_tile(kt + 3, (kt + 3) & 3);

        uint32_t abase = dsb + (uint32_t)(kt & 3) * STAGE;
        uint32_t bbase = abase + 10240u;
        #pragma unroll
        for (int kk = 0; kk < 2; ++kk) {     // two k16 steps per 32-half tile
            int kb = kk * 8;                 // half2 col base
            uint32_t af[4][4], bf[8][2];
            #pragma unroll
            for (int im = 0; im < 4; im++)
                ldsm4(af[im][0], af[im][1], af[im][2], af[im][3],
                      abase + (uint32_t)(((a_row + im * 16) * LDS_ + kb + a_col) * 4));
            #pragma unroll
            for (int p = 0; p < 4; p++)
                ldsm4(bf[2 * p][0], bf[2 * p][1], bf[2 * p + 1][0], bf[2 * p + 1][1],
                      bbase + (uint32_t)(((b_row + 16 * p) * LDS_ + kb + b_col) * 4));
            #pragma unroll
            for (int im = 0; im < 4; im++)
                #pragma unroll
                for (int in = 0; in < 8; in++)
                    mma_f16(acc[im][in], af[im], bf[in]);
        }
    }
    __syncthreads();                         // all compute done; reuse smem

    if (MODE == 0) {
        uint32_t* sep = (uint32_t*)dynsm;
        #pragma unroll
        for (int im = 0; im < 4; im++)
            #pragma unroll
            for (int in = 0; in < 8; in++) {
                int r = wm + im * 16 + g;
                int c2 = (wn >> 1) + in * 4 + tg;
                __half2 lo = __floats2half2_rn(acc[im][in][0], acc[im][in][1]);
                __half2 hi = __floats2half2_rn(acc[im][in][2], acc[im][in][3]);
                sep[r * 65 + c2]       = *(uint32_t*)&lo;
                sep[(r + 8) * 65 + c2] = *(uint32_t*)&hi;
            }
        __syncthreads();
        #pragma unroll
        for (int i = 0; i < 64; i++) {       // 8192 half2 / 128 threads
            int idx = tid + i * 128;
            int row = idx >> 6, c2 = idx & 63;
            *(__half2*)&g_qkv[(size_t)(m0 + row) * NQKV + n0 + 2 * c2] =
                *(__half2*)&sep[row * 65 + c2];
        }
    } else {
        float* sep = (float*)dynsm;
        #pragma unroll
        for (int im = 0; im < 4; im++)
            #pragma unroll
            for (int in = 0; in < 8; in++) {
                int r = wm + im * 16 + g;
                int c = wn + in * 8 + tg * 2;
                sep[r * 129 + c]           = acc[im][in][0];
                sep[r * 129 + c + 1]       = acc[im][in][1];
                sep[(r + 8) * 129 + c]     = acc[im][in][2];
                sep[(r + 8) * 129 + c + 1] = acc[im][in][3];
            }
        __syncthreads();
        int tt = m0 >> 10, hwb = m0 & 1023;
        #pragma unroll
        for (int i = 0; i < 128; i++) {      // 16384 floats / 128 threads
            int idx = tid + i * 128;
            int c = idx >> 7, row = idx & 127;
            size_t oi = ((size_t)tt * C_DIM + n0 + c) * HW_DIM + hwb + row;
            out[oi] = sep[row * 129 + c] + g_pb[n0 + c] + xres[oi];
        }
    }
}

// ---------------------------------------------------------------------------
// Attention: one warp per token; fp16 raw Q/K/V; qb/kb biases in half2
// (fp32 accumulate); bv moved to gemm1 epilogue via pb.
// ---------------------------------------------------------------------------
__global__ void __launch_bounds__(256) attn_kernel() {
    int wid = threadIdx.x >> 5, lane = threadIdx.x & 31;
    int token = blockIdx.x * 8 + wid;
    int t = token >> 10, hw = token & 1023;
    const int offs[4] = {-2, -1, 1, 2};
    size_t kvbase[4];
    #pragma unroll
    for (int fi = 0; fi < 4; fi++) {
        int ts = t + offs[fi];
        ts = ts < 0 ? 0 : (ts > 15 ? 15 : ts);
        kvbase[fi] = (size_t)((ts << 10) | hw) * NQKV;
    }
    const __half2* Q2 = (const __half2*)(g_qkv + (size_t)token * NQKV);
    __half2* O2 = (__half2*)(g_attn + (size_t)token * C_DIM);

    #pragma unroll
    for (int h = 0; h < 8; ++h) {
        int cb2 = h * 32;                          // half2 index base
        float2 qb = __half22float2(g_qbh[cb2 + lane]);
        float2 q = __half22float2(Q2[cb2 + lane]);
        q.x += qb.x; q.y += qb.y;
        float s[4];
        #pragma unroll
        for (int fi = 0; fi < 4; fi++) {
            const __half2* K2 = (const __half2*)(g_qkv + kvbase[fi] + 512) + cb2;
            float2 k = __half22float2(K2[lane]);
            float2 kb = __half22float2(g_kbh[fi * 256 + cb2 + lane]);
            float p = q.x * (k.x + kb.x) + q.y * (k.y + kb.y);
            for (int o = 16; o; o >>= 1) p += __shfl_xor_sync(0xffffffffu, p, o);
            s[fi] = p * 0.125f;                    // dh^-0.5, dh=64
        }
        float m = fmaxf(fmaxf(s[0], s[1]), fmaxf(s[2], s[3]));
        float e[4], sum = 0.f;
        #pragma unroll
        for (int fi = 0; fi < 4; fi++) { e[fi] = __expf(s[fi] - m); sum += e[fi]; }
        float inv = 1.f / sum;
        float ax = 0.f, ay = 0.f;
        #pragma unroll
        for (int fi = 0; fi < 4; fi++) {
            const __half2* V2 = (const __half2*)(g_qkv + kvbase[fi] + 1024) + cb2;
            float2 v = __half22float2(V2[lane]);
            float p = e[fi] * inv;
            ax += p * v.x;
            ay += p * v.y;
        }
        O2[cb2 + lane] = __floats2half2_rn(ax, ay);
    }
}

// ---------------------------------------------------------------------------
extern "C" void kernel_launch(void* const* d_in, const int* in_sizes, int n_in,
                              void* d_out, int out_size) {
    const float* x       = (const float*)d_in[0];
    const float* w_q     = (const float*)d_in[1];
    const float* b_q     = (const float*)d_in[2];
    const float* w_k     = (const float*)d_in[3];
    const float* b_k     = (const float*)d_in[4];
    const float* w_v     = (const float*)d_in[5];
    const float* b_v     = (const float*)d_in[6];
    const float* w_proj  = (const float*)d_in[7];
    const float* b_proj  = (const float*)d_in[8];
    const float* gn_s    = (const float*)d_in[9];
    const float* gn_b    = (const float*)d_in[10];
    float* out = (float*)d_out;

    // Unconditional every call: deterministic, not stream-ordered (capture-safe).
    cudaFuncSetAttribute(gemm_fp16<0>, cudaFuncAttributeMaxDynamicSharedMemorySize, GEMM_DYNSMEM);
    cudaFuncSetAttribute(gemm_fp16<1>, cudaFuncAttributeMaxDynamicSharedMemorySize, GEMM_DYNSMEM);

    fused_prep<<<1664, 256>>>(x, w_q, w_k, w_v, w_proj, b_q, b_k, b_v, b_proj);
    gn_apply<<<dim3(32, 16, 16), dim3(32, 8)>>>(x, gn_s, gn_b);
    gemm_fp16<0><<<dim3(12, 128), 128, GEMM_DYNSMEM>>>(nullptr, nullptr);
    attn_kernel<<<2048, 256>>>();
    gemm_fp16<1><<<dim3(4, 128), 128, GEMM_DYNSMEM>>>(x, out);
}

// round 17
// speedup vs baseline: 1.1895x; 1.1895x over previous
#include <cuda_runtime.h>
#include <cuda_fp16.h>
#include <cstdint>

// ---------------------------------------------------------------------------
// TemporalAttention, B200 (compute_100 target -> legacy mma.sync path).
// R17 = R14 baseline (199.6us verified) + ONLY the attn half2-bias change
// from R15 (qb/kb stored half2). bv stays in attn; gemm_fp16 signature,
// b_proj epilogue, and fused_prep structure identical to R14.
// Bisect: isolates {attn half2 biases} from {gemm pb-fold} (R15 regressed).
// Order: fused_prep, gn_apply, gemm0, attn, gemm1
// ---------------------------------------------------------------------------

#define T_DIM   16
#define C_DIM   512
#define HW_DIM  1024
#define NTOK    16384
#define NQKV    1536
#define NGRP    32
#define GN_EPS  1e-5f

__device__ __half  g_xn  [NTOK * C_DIM];
__device__ __half  g_qkv [NTOK * NQKV];     // raw Q|K|V (biases applied in attn)
__device__ __half  g_attn[NTOK * C_DIM];
__device__ __half  g_wcat[NQKV * C_DIM];
__device__ __half  g_wproj[C_DIM * C_DIM];
__device__ float   g_mu[512];
__device__ float   g_rs[512];
__device__ __half2 g_qbh[256];              // half2(b_q + t_mid @ Wq^T)
__device__ __half2 g_kbh[4 * 256];          // half2(b_k + t_rest[fi] @ Wk^T)

// ---------------------------------------------------------------------------
// fused_prep: blocks [0,512) GroupNorm stats; [512,1536) weight fp16 convert;
// [1536,1600) qb/kb bias precompute (one warp per output channel).
// All three are input/output disjoint -> safe to run concurrently.
// ---------------------------------------------------------------------------
__global__ void __launch_bounds__(256) fused_prep(const float* __restrict__ x,
                                                  const float* __restrict__ w_q,
                                                  const float* __restrict__ w_k,
                                                  const float* __restrict__ w_v,
                                                  const float* __restrict__ w_proj,
                                                  const float* __restrict__ b_q,
                                                  const float* __restrict__ b_k) {
    if (blockIdx.x < 512) {
        // ---- GroupNorm statistics: one block per (t, group) ----
        int b = blockIdx.x;
        const float4* base = (const float4*)(x + (size_t)b * 16384);
        float s = 0.f, s2 = 0.f;
        #pragma unroll
        for (int i = 0; i < 16; i++) {
            float4 v = base[threadIdx.x + i * 256];
            s  += v.x + v.y + v.z + v.w;
            s2 += v.x * v.x + v.y * v.y + v.z * v.z + v.w * v.w;
        }
        for (int o = 16; o; o >>= 1) {
            s  += __shfl_xor_sync(0xffffffffu, s,  o);
            s2 += __shfl_xor_sync(0xffffffffu, s2, o);
        }
        __shared__ float rs[8], rs2[8];
        int wid = threadIdx.x >> 5;
        if ((threadIdx.x & 31) == 0) { rs[wid] = s; rs2[wid] = s2; }
        __syncthreads();
        if (threadIdx.x == 0) {
            float a = 0.f, a2 = 0.f;
            #pragma unroll
            for (int i = 0; i < 8; i++) { a += rs[i]; a2 += rs2[i]; }
            float mu  = a  * (1.f / 16384.f);
            float var = a2 * (1.f / 16384.f) - mu * mu;
            g_mu[b] = mu;
            g_rs[b] = rsqrtf(var + GN_EPS);
        }
        return;
    }
    if (blockIdx.x < 1536) {
        // ---- weight conversion to fp16 ----
        int i = (blockIdx.x - 512) * 256 + threadIdx.x;
        g_wcat[i]          = __float2half_rn(w_q[i]);
        g_wcat[262144 + i] = __float2half_rn(w_k[i]);
        g_wcat[524288 + i] = __float2half_rn(w_v[i]);
        g_wproj[i]         = __float2half_rn(w_proj[i]);
        return;
    }
    // ---- qb/kb: one warp per output channel j, stored as half ----
    int wid = threadIdx.x >> 5, lane = threadIdx.x & 31;
    int j = (blockIdx.x - 1536) * 8 + wid;        // 0..511
    float aq = 0.f, a0 = 0.f, a1 = 0.f, a2 = 0.f, a3 = 0.f;
    for (int c = lane; c < 512; c += 32) {
        float wq = w_q[j * 512 + c];
        float wk = w_k[j * 512 + c];
        int ci = (c < 256) ? c : c - 256;
        float fr = __expf(-0.035977892f * (float)ci);    // ln(1e4)/256
        float s1, c1, s2, c2;
        __sincosf(fr, &s1, &c1);
        __sincosf(2.f * fr, &s2, &c2);
        if (c < 256) {
            aq += wq;
            a0 += c2 * wk; a1 += c1 * wk; a2 += c1 * wk; a3 += c2 * wk;
        } else {
            a0 -= s2 * wk; a1 -= s1 * wk; a2 += s1 * wk; a3 += s2 * wk;
        }
    }
    for (int o = 16; o; o >>= 1) {
        aq += __shfl_xor_sync(0xffffffffu, aq, o);
        a0 += __shfl_xor_sync(0xffffffffu, a0, o);
        a1 += __shfl_xor_sync(0xffffffffu, a1, o);
        a2 += __shfl_xor_sync(0xffffffffu, a2, o);
        a3 += __shfl_xor_sync(0xffffffffu, a3, o);
    }
    if (lane == 0) {
        float bk = b_k[j];
        __half* qh = (__half*)g_qbh;
        __half* kh = (__half*)g_kbh;
        qh[j]           = __float2half_rn(aq + b_q[j]);
        kh[0 * 512 + j] = __float2half_rn(a0 + bk);
        kh[1 * 512 + j] = __float2half_rn(a1 + bk);
        kh[2 * 512 + j] = __float2half_rn(a2 + bk);
        kh[3 * 512 + j] = __float2half_rn(a3 + bk);
    }
}

// ---------------------------------------------------------------------------
// GN apply + transpose [t,c,hw] -> [token, c], fp16 output
// ---------------------------------------------------------------------------
__global__ void __launch_bounds__(256) gn_apply(const float* __restrict__ x,
                                                const float* __restrict__ gs,
                                                const float* __restrict__ gb) {
    __shared__ float tile[32][33];
    int t   = blockIdx.z;
    int c0  = blockIdx.y * 32;
    int hw0 = blockIdx.x * 32;
    #pragma unroll
    for (int i = 0; i < 4; i++) {
        int c = c0 + threadIdx.y + i * 8;
        float v = x[((size_t)t * C_DIM + c) * HW_DIM + hw0 + threadIdx.x];
        int grp = c >> 4;
        v = (v - g_mu[t * NGRP + grp]) * g_rs[t * NGRP + grp] * gs[c] + gb[c];
        tile[threadIdx.y + i * 8][threadIdx.x] = v;
    }
    __syncthreads();
    #pragma unroll
    for (int i = 0; i < 4; i++) {
        int hw = hw0 + threadIdx.y + i * 8;
        g_xn[((size_t)t * HW_DIM + hw) * C_DIM + c0 + threadIdx.x] =
            __float2half_rn(tile[threadIdx.x][threadIdx.y + i * 8]);
    }
}

// ---------------------------------------------------------------------------
// FP16 GEMM (identical to R14): 128x128x32 CTA tile, 4 warps, warp tile
// 64x64, 4-stage cp.async pipeline, ldmatrix.x4 + mma.sync.m16n8k16.
// ---------------------------------------------------------------------------
__device__ __forceinline__ void cpa16(uint32_t dst, const void* src) {
    asm volatile("cp.async.cg.shared.global [%0], [%1], 16;\n" :: "r"(dst), "l"(src));
}
__device__ __forceinline__ void mma_f16(float* c, const uint32_t* a, const uint32_t* b) {
    asm volatile(
        "mma.sync.aligned.m16n8k16.row.col.f32.f16.f16.f32 "
        "{%0,%1,%2,%3}, {%4,%5,%6,%7}, {%8,%9}, {%0,%1,%2,%3};"
        : "+f"(c[0]), "+f"(c[1]), "+f"(c[2]), "+f"(c[3])
        : "r"(a[0]), "r"(a[1]), "r"(a[2]), "r"(a[3]), "r"(b[0]), "r"(b[1]));
}
__device__ __forceinline__ void ldsm4(uint32_t& r0, uint32_t& r1, uint32_t& r2,
                                      uint32_t& r3, uint32_t a) {
    asm volatile("ldmatrix.sync.aligned.m8n8.x4.shared.b16 {%0,%1,%2,%3}, [%4];"
                 : "=r"(r0), "=r"(r1), "=r"(r2), "=r"(r3) : "r"(a));
}

#define GEMM_DYNSMEM 81920

template <int MODE>
__global__ void __launch_bounds__(128, 2) gemm_fp16(const float* __restrict__ xres,
                                                    float* __restrict__ out,
                                                    const float* __restrict__ b_proj) {
    constexpr int LDS_ = 20;                 // pitch in half2 units (80B/row)
    constexpr uint32_t STAGE = 128 * LDS_ * 4 * 2;   // 20480B (A+B)
    const __half* A = (MODE == 0) ? g_xn   : g_attn;
    const __half* B = (MODE == 0) ? g_wcat : g_wproj;

    extern __shared__ __align__(16) uint8_t dynsm[];
    uint32_t dsb = (uint32_t)__cvta_generic_to_shared(dynsm);

    int m0 = blockIdx.y * 128;
    int n0 = blockIdx.x * 128;
    int tid = threadIdx.x;
    int wid = tid >> 5, lane = tid & 31;
    int wm = (wid & 1) * 64, wn = (wid >> 1) * 64;   // 2x2 warp grid
    int g = lane >> 2, tg = lane & 3;

    int a_row = wm + (lane & 15);                       // + im*16
    int a_col = (lane >> 4) << 2;                       // 0 or 4 (uint32)
    int b_row = wn + ((lane >> 4) << 3) + (lane & 7);   // + 16*pair (4 pairs)
    int b_col = ((lane >> 3) & 1) << 2;                 // 0 or 4

    auto load_tile = [&](int kt, int slot) {
        uint32_t base = dsb + (uint32_t)slot * STAGE;
        #pragma unroll
        for (int j = 0; j < 4; j++) {
            int id = tid + j * 128;
            int row = id >> 2, c = id & 3;
            uint32_t soff = (uint32_t)((row * LDS_ + c * 4) * 4);
            cpa16(base + soff, A + (size_t)(m0 + row) * 512 + kt * 32 + c * 8);
            cpa16(base + 10240u + soff, B + (size_t)(n0 + row) * 512 + kt * 32 + c * 8);
        }
        asm volatile("cp.async.commit_group;\n" ::);
    };

    float acc[4][8][4];
    #pragma unroll
    for (int i = 0; i < 4; i++)
        #pragma unroll
        for (int j = 0; j < 8; j++)
            #pragma unroll
            for (int r = 0; r < 4; r++) acc[i][j][r] = 0.f;

    load_tile(0, 0); load_tile(1, 1); load_tile(2, 2);

    for (int kt = 0; kt < 16; ++kt) {        // K = 512 / 32
        if (kt <= 13)      asm volatile("cp.async.wait_group 2;\n" ::);
        else if (kt == 14) asm volatile("cp.async.wait_group 1;\n" ::);
        else               asm volatile("cp.async.wait_group 0;\n" ::);
        __syncthreads();                     // stage kt visible; kt-1 consumed by all

        if (kt + 3 < 16) load_tile(kt + 3, (kt + 3) & 3);

        uint32_t abase = dsb + (uint32_t)(kt & 3) * STAGE;
        uint32_t bbase = abase + 10240u;
        #pragma unroll
        for (int kk = 0; kk < 2; ++kk) {     // two k16 steps per 32-half tile
            int kb = kk * 8;                 // half2 col base
            uint32_t af[4][4], bf[8][2];
            #pragma unroll
            for (int im = 0; im < 4; im++)
                ldsm4(af[im][0], af[im][1], af[im][2], af[im][3],
                      abase + (uint32_t)(((a_row + im * 16) * LDS_ + kb + a_col) * 4));
            #pragma unroll
            for (int p = 0; p < 4; p++)
                ldsm4(bf[2 * p][0], bf[2 * p][1], bf[2 * p + 1][0], bf[2 * p + 1][1],
                      bbase + (uint32_t)(((b_row + 16 * p) * LDS_ + kb + b_col) * 4));
            #pragma unroll
            for (int im = 0; im < 4; im++)
                #pragma unroll
                for (int in = 0; in < 8; in++)
                    mma_f16(acc[im][in], af[im], bf[in]);
        }
    }
    __syncthreads();                         // all compute done; reuse smem

    if (MODE == 0) {
        uint32_t* sep = (uint32_t*)dynsm;
        #pragma unroll
        for (int im = 0; im < 4; im++)
            #pragma unroll
            for (int in = 0; in < 8; in++) {
                int r = wm + im * 16 + g;
                int c2 = (wn >> 1) + in * 4 + tg;
                __half2 lo = __floats2half2_rn(acc[im][in][0], acc[im][in][1]);
                __half2 hi = __floats2half2_rn(acc[im][in][2], acc[im][in][3]);
                sep[r * 65 + c2]       = *(uint32_t*)&lo;
                sep[(r + 8) * 65 + c2] = *(uint32_t*)&hi;
            }
        __syncthreads();
        #pragma unroll
        for (int i = 0; i < 64; i++) {       // 8192 half2 / 128 threads
            int idx = tid + i * 128;
            int row = idx >> 6, c2 = idx & 63;
            *(__half2*)&g_qkv[(size_t)(m0 + row) * NQKV + n0 + 2 * c2] =
                *(__half2*)&sep[row * 65 + c2];
        }
    } else {
        float* sep = (float*)dynsm;
        #pragma unroll
        for (int im = 0; im < 4; im++)
            #pragma unroll
            for (int in = 0; in < 8; in++) {
                int r = wm + im * 16 + g;
                int c = wn + in * 8 + tg * 2;
                sep[r * 129 + c]           = acc[im][in][0];
                sep[r * 129 + c + 1]       = acc[im][in][1];
                sep[(r + 8) * 129 + c]     = acc[im][in][2];
                sep[(r + 8) * 129 + c + 1] = acc[im][in][3];
            }
        __syncthreads();
        int tt = m0 >> 10, hwb = m0 & 1023;
        #pragma unroll
        for (int i = 0; i < 128; i++) {      // 16384 floats / 128 threads
            int idx = tid + i * 128;
            int c = idx >> 7, row = idx & 127;
            size_t oi = ((size_t)tt * C_DIM + n0 + c) * HW_DIM + hwb + row;
            out[oi] = sep[row * 129 + c] + b_proj[n0 + c] + xres[oi];
        }
    }
}

// ---------------------------------------------------------------------------
// Attention (R14 structure, half2 biases): one warp per token; fp16 raw
// Q/K/V; qb/kb read as half2 (fp32 accumulate); bv added here in fp32.
// ---------------------------------------------------------------------------
__global__ void __launch_bounds__(256) attn_kernel(const float* __restrict__ b_v) {
    int wid = threadIdx.x >> 5, lane = threadIdx.x & 31;
    int token = blockIdx.x * 8 + wid;
    int t = token >> 10, hw = token & 1023;
    const int offs[4] = {-2, -1, 1, 2};
    size_t kvbase[4];
    #pragma unroll
    for (int fi = 0; fi < 4; fi++) {
        int ts = t + offs[fi];
        ts = ts < 0 ? 0 : (ts > 15 ? 15 : ts);
        kvbase[fi] = (size_t)((ts << 10) | hw) * NQKV;
    }
    const __half2* Q2 = (const __half2*)(g_qkv + (size_t)token * NQKV);
    __half2* O2 = (__half2*)(g_attn + (size_t)token * C_DIM);

    #pragma unroll
    for (int h = 0; h < 8; ++h) {
        int cb2 = h * 32;                          // half2 index base
        float2 qb = __half22float2(g_qbh[cb2 + lane]);
        float2 q = __half22float2(Q2[cb2 + lane]);
        q.x += qb.x; q.y += qb.y;
        float s[4];
        #pragma unroll
        for (int fi = 0; fi < 4; fi++) {
            const __half2* K2 = (const __half2*)(g_qkv + kvbase[fi] + 512) + cb2;
            float2 k = __half22float2(K2[lane]);
            float2 kb = __half22float2(g_kbh[fi * 256 + cb2 + lane]);
            float p = q.x * (k.x + kb.x) + q.y * (k.y + kb.y);
            for (int o = 16; o; o >>= 1) p += __shfl_xor_sync(0xffffffffu, p, o);
            s[fi] = p * 0.125f;                    // dh^-0.5, dh=64
        }
        float m = fmaxf(fmaxf(s[0], s[1]), fmaxf(s[2], s[3]));
        float e[4], sum = 0.f;
        #pragma unroll
        for (int fi = 0; fi < 4; fi++) { e[fi] = __expf(s[fi] - m); sum += e[fi]; }
        float inv = 1.f / sum;
        float ax = 0.f, ay = 0.f;
        #pragma unroll
        for (int fi = 0; fi < 4; fi++) {
            const __half2* V2 = (const __half2*)(g_qkv + kvbase[fi] + 1024) + cb2;
            float2 v = __half22float2(V2[lane]);
            float p = e[fi] * inv;
            ax += p * v.x;
            ay += p * v.y;
        }
        float2 bv = ((const float2*)b_v)[cb2 + lane];
        O2[cb2 + lane] = __floats2half2_rn(ax + bv.x, ay + bv.y);
    }
}

// ---------------------------------------------------------------------------
extern "C" void kernel_launch(void* const* d_in, const int* in_sizes, int n_in,
                              void* d_out, int out_size) {
    const float* x       = (const float*)d_in[0];
    const float* w_q     = (const float*)d_in[1];
    const float* b_q     = (const float*)d_in[2];
    const float* w_k     = (const float*)d_in[3];
    const float* b_k     = (const float*)d_in[4];
    const float* w_v     = (const float*)d_in[5];
    const float* b_v     = (const float*)d_in[6];
    const float* w_proj  = (const float*)d_in[7];
    const float* b_proj  = (const float*)d_in[8];
    const float* gn_s    = (const float*)d_in[9];
    const float* gn_b    = (const float*)d_in[10];
    float* out = (float*)d_out;

    // Unconditional every call: deterministic, not stream-ordered (capture-safe).
    cudaFuncSetAttribute(gemm_fp16<0>, cudaFuncAttributeMaxDynamicSharedMemorySize, GEMM_DYNSMEM);
    cudaFuncSetAttribute(gemm_fp16<1>, cudaFuncAttributeMaxDynamicSharedMemorySize, GEMM_DYNSMEM);

    fused_prep<<<1600, 256>>>(x, w_q, w_k, w_v, w_proj, b_q, b_k);
    gn_apply<<<dim3(32, 16, 16), dim3(32, 8)>>>(x, gn_s, gn_b);
    gemm_fp16<0><<<dim3(12, 128), 128, GEMM_DYNSMEM>>>(nullptr, nullptr, nullptr);
    attn_kernel<<<2048, 256>>>(b_v);
    gemm_fp16<1><<<dim3(4, 128), 128, GEMM_DYNSMEM>>>(x, out, b_proj);
}